// round 3
// baseline (speedup 1.0000x reference)
#include <cuda_runtime.h>
#include <cuda_bf16.h>
#include <cstdint>

// Problem: x [16, 256, 128, 128] f32.
//  1) weight[b,c] = mean over H,W
//  2) idx[b,:] = argsort(weight[b]) ascending, take first 16 (stable)
//  3) out[b,k,:,:] = x[b, idx[b,k], :, :]
//
// R3: single persistent kernel. Every block computes one plane's mean and
// bumps a per-batch counter. The last 16 blocks of each batch additionally
// wait for their batch's counter, rank the 256 means (stable), and stream
// one selected 64KB plane to the output — overlapped with the remaining
// batches' DRAM-bound mean work.

#define B 16
#define C 256
#define HW 16384          // 128*128
#define K 16

__device__ float g_weight[B * C];
__device__ int   g_count[B];          // reset to 0 by memsetAsync each launch

__global__ __launch_bounds__(256) void fused_kernel(const float* __restrict__ x,
                                                    float* __restrict__ out) {
    const int bc = blockIdx.x;                        // 0..4095
    const int b  = bc >> 8;
    const int t  = threadIdx.x;

    // ---- Phase 1: mean of plane bc (DRAM-bound, 64KB/block) ----
    {
        const float4* __restrict__ p =
            reinterpret_cast<const float4*>(x + (size_t)bc * HW);
        float s0 = 0.f, s1 = 0.f, s2 = 0.f, s3 = 0.f;
#pragma unroll
        for (int i = 0; i < 16; i += 4) {
            float4 v0 = __ldg(&p[t + (i + 0) * 256]);
            float4 v1 = __ldg(&p[t + (i + 1) * 256]);
            float4 v2 = __ldg(&p[t + (i + 2) * 256]);
            float4 v3 = __ldg(&p[t + (i + 3) * 256]);
            s0 += (v0.x + v0.y) + (v0.z + v0.w);
            s1 += (v1.x + v1.y) + (v1.z + v1.w);
            s2 += (v2.x + v2.y) + (v2.z + v2.w);
            s3 += (v3.x + v3.y) + (v3.z + v3.w);
        }
        float s = (s0 + s1) + (s2 + s3);
#pragma unroll
        for (int off = 16; off > 0; off >>= 1)
            s += __shfl_down_sync(0xFFFFFFFFu, s, off);

        __shared__ float sred[8];
        if ((t & 31) == 0) sred[t >> 5] = s;
        __syncthreads();
        if (t < 8) {
            float v = sred[t];
#pragma unroll
            for (int off = 4; off > 0; off >>= 1)
                v += __shfl_down_sync(0xFFu, v, off);
            if (t == 0) {
                g_weight[bc] = v * (1.0f / (float)HW);
                __threadfence();
                atomicAdd(&g_count[b], 1);
            }
        }
    }

    // ---- Phase 2: last 16 blocks of each batch own one output plane ----
    const int r = bc & 255;
    if (r < 240) return;
    const int k = r - 240;                            // 0..15

    if (t == 0) {
        while (atomicAdd(&g_count[b], 0) < C) __nanosleep(128);
    }
    __syncthreads();                                  // all threads see handoff

    __shared__ float sw[C];
    __shared__ int sel;
    sw[t] = __ldcg(&g_weight[b * C + t]);             // L2-coherent read
    __syncthreads();

    const float v = sw[t];
    int rank = 0;
#pragma unroll 8
    for (int j = 0; j < C; ++j) {
        const float u = sw[j];
        rank += (u < v) || (u == v && j < t);
    }
    if (rank == k) sel = t;                           // exactly one thread hits
    __syncthreads();
    const int c = sel;

    const float4* __restrict__ src =
        reinterpret_cast<const float4*>(x + ((size_t)b * C + c) * HW);
    float4* __restrict__ dst =
        reinterpret_cast<float4*>(out + (size_t)(b * K + k) * HW);

#pragma unroll
    for (int i = 0; i < 16; ++i) {
        float4 w = __ldg(&src[t + i * 256]);
        __stcs(&dst[t + i * 256], w);                 // streaming store
    }
}

// ---------------------------------------------------------------------------
extern "C" void kernel_launch(void* const* d_in, const int* in_sizes, int n_in,
                              void* d_out, int out_size) {
    const float* x = (const float*)d_in[0];
    float* out = (float*)d_out;

    void* cptr = nullptr;
    cudaGetSymbolAddress(&cptr, g_count);
    cudaMemsetAsync(cptr, 0, B * sizeof(int));        // graph-capturable node

    fused_kernel<<<B * C, 256>>>(x, out);
}